// round 16
// baseline (speedup 1.0000x reference)
#include <cuda_runtime.h>
#include <math.h>

#define NB 256
#define NS 512
#define ND 128
#define NH 256
#define NHH 128
#define NL 64

#define NG   16   // batch groups
#define BPG  16   // batches per group
#define CLU  8    // CTAs per cluster (j-split)

// ---------------- device-global scratch (no allocation allowed) ----------------
__device__ float  g_emb[(size_t)NB * NS * ND];            // 64 MB   emb[b][s][d]
__device__ float  g_h2seq[(size_t)NS * NG * NH * BPG];    // 134 MB  [t][g][j][b]
__device__ float  g_h1x[2 * NG * NH * BPG];               // enc1 h exchange [par][g][k][b]
__device__ float  g_h2x[2 * NG * NHH * BPG];              // enc2 h exchange
__device__ float  g_hd1x[2 * NG * NHH * BPG];             // dec1 h exchange
__device__ float  g_hd2x[2 * NG * NH * BPG];              // dec2 h exchange
__device__ float  g_lat[NB * NL];                         // latent [b][l]
__device__ float  g_gi1[NB * 3 * NHH];                    // decoder const gi [b][384]
__device__ double g_losspart[1024];

static __device__ __forceinline__ float sigf(float v) { return 1.0f / (1.0f + expf(-v)); }

static __device__ __forceinline__ void cluster_sync_all() {
    __threadfence();   // order global h stores before the barrier
    asm volatile("barrier.cluster.arrive.aligned;" ::: "memory");
    asm volatile("barrier.cluster.wait.aligned;"   ::: "memory");
}

// accumulate 3 gates x 2 batches
static __device__ __forceinline__ void fma6(float wr, float wz, float wn, float2 h,
                                            float& ar, float& az, float& an,
                                            float& cr, float& cz, float& cn) {
    ar += wr * h.x; cr += wr * h.y;
    az += wz * h.x; cz += wz * h.y;
    an += wn * h.x; cn += wn * h.y;
}

// ---------------- init ----------------
__global__ void init_kernel() {
    int i = blockIdx.x * blockDim.x + threadIdx.x;
    if (i < 1024) g_losspart[i] = 0.0;
}

// ---------------- embedding ----------------
__global__ __launch_bounds__(256) void emb_kernel(const int* __restrict__ tok,
                                                  const float* __restrict__ pw,
                                                  const float* __restrict__ sw) {
    const int n4 = NB * NS * ND / 4;
    const float4* p4 = (const float4*)pw;
    const float4* s4 = (const float4*)sw;
    float4* e4 = (float4*)g_emb;
    for (int i = blockIdx.x * blockDim.x + threadIdx.x; i < n4; i += gridDim.x * blockDim.x) {
        int bs = i >> 5;
        int c = i & 31;
        int p = tok[(size_t)bs * 2 + 0];
        int q = tok[(size_t)bs * 2 + 1];
        float4 a = p4[(size_t)p * 32 + c];
        float4 b = s4[(size_t)q * 32 + c];
        e4[i] = make_float4(a.x + b.x, a.y + b.y, a.z + b.z, a.w + b.w);
    }
}

// ======================= ENCODER: persistent over all 512 steps =======================
// 128 CTAs = 16 clusters of 8; cluster owns 16 batches; CTA rank owns a j-slice.
// smem state layout [k][b] (b fast) -> conflict-free float2 reads per batch pair.
__global__ __launch_bounds__(256, 1) __cluster_dims__(CLU, 1, 1)
void enc_kernel(const float* __restrict__ e1_Wih, const float* __restrict__ e1_Whh,
                const float* __restrict__ e1_bih, const float* __restrict__ e1_bhh,
                const float* __restrict__ e2_Wih, const float* __restrict__ e2_Whh,
                const float* __restrict__ e2_bih, const float* __restrict__ e2_bhh) {
    __shared__ float sh_h1[NH * BPG];    // 16 KB
    __shared__ float sh_h2[NHH * BPG];   // 8 KB
    __shared__ float sh_x[ND * BPG];     // 8 KB

    const int tid = threadIdx.x;
    const int rank = blockIdx.x & (CLU - 1);
    const int g = blockIdx.x >> 3;
    const int bp = tid & 7;              // batch pair (b = 2bp, 2bp+1)

    {
        float4 z = make_float4(0.f, 0.f, 0.f, 0.f);
        float4* h1 = (float4*)sh_h1;
        float4* h2 = (float4*)sh_h2;
        for (int p = 0; p < 4; p++) h1[tid + p * 256] = z;
        for (int p = 0; p < 2; p++) h2[tid + p * 256] = z;
    }

    const int j1 = rank * 32 + (tid >> 3);                 // enc1 j
    const float b1r  = e1_bih[j1] + e1_bhh[j1];
    const float b1z  = e1_bih[NH + j1] + e1_bhh[NH + j1];
    const float b1in = e1_bih[2 * NH + j1];
    const float b1hn = e1_bhh[2 * NH + j1];
    const float4* w1r_h = (const float4*)(e1_Whh + (size_t)j1 * NH);
    const float4* w1z_h = (const float4*)(e1_Whh + (size_t)(NH + j1) * NH);
    const float4* w1n_h = (const float4*)(e1_Whh + (size_t)(2 * NH + j1) * NH);
    const float4* w1r_x = (const float4*)(e1_Wih + (size_t)j1 * ND);
    const float4* w1z_x = (const float4*)(e1_Wih + (size_t)(NH + j1) * ND);
    const float4* w1n_x = (const float4*)(e1_Wih + (size_t)(2 * NH + j1) * ND);

    const int j2 = rank * 16 + (tid >> 3);                 // enc2 j (tid<128)
    float b2r = 0.f, b2z = 0.f, b2in = 0.f, b2hn = 0.f;
    const float4 *w2r_h = 0, *w2z_h = 0, *w2n_h = 0, *w2r_x = 0, *w2z_x = 0, *w2n_x = 0;
    if (tid < 128) {
        b2r  = e2_bih[j2] + e2_bhh[j2];
        b2z  = e2_bih[NHH + j2] + e2_bhh[NHH + j2];
        b2in = e2_bih[2 * NHH + j2];
        b2hn = e2_bhh[2 * NHH + j2];
        w2r_h = (const float4*)(e2_Whh + (size_t)j2 * NHH);
        w2z_h = (const float4*)(e2_Whh + (size_t)(NHH + j2) * NHH);
        w2n_h = (const float4*)(e2_Whh + (size_t)(2 * NHH + j2) * NHH);
        w2r_x = (const float4*)(e2_Wih + (size_t)j2 * NH);
        w2z_x = (const float4*)(e2_Wih + (size_t)(NHH + j2) * NH);
        w2n_x = (const float4*)(e2_Wih + (size_t)(2 * NHH + j2) * NH);
    }
    __syncthreads();

    const float2* h1p = (const float2*)sh_h1;
    const float2* h2p = (const float2*)sh_h2;
    const float2* xp  = (const float2*)sh_x;

    for (int t = 0; t < NS; t++) {
        const int par = t & 1;

        // stage x = emb[:, t, :] transposed -> sh_x[k][b]
        for (int p = 0; p < 2; p++) {
            int idx = tid + p * 256;
            int b = idx >> 5, kc = idx & 31;
            float4 v = __ldg((const float4*)g_emb + ((size_t)(g * BPG + b) * NS + t) * 32 + kc);
            sh_x[(kc * 4 + 0) * BPG + b] = v.x;
            sh_x[(kc * 4 + 1) * BPG + b] = v.y;
            sh_x[(kc * 4 + 2) * BPG + b] = v.z;
            sh_x[(kc * 4 + 3) * BPG + b] = v.w;
        }
        __syncthreads();

        // enc1 gates for (j1, 2 batches)
        float ar = b1r, az = b1z, ain = b1in, ahn = b1hn;
        float cr = b1r, cz = b1z, cin = b1in, chn = b1hn;
#pragma unroll 2
        for (int kc = 0; kc < NH / 4; kc++) {
            float4 wr = __ldg(w1r_h + kc), wz = __ldg(w1z_h + kc), wn = __ldg(w1n_h + kc);
            fma6(wr.x, wz.x, wn.x, h1p[(kc * 4 + 0) * 8 + bp], ar, az, ahn, cr, cz, chn);
            fma6(wr.y, wz.y, wn.y, h1p[(kc * 4 + 1) * 8 + bp], ar, az, ahn, cr, cz, chn);
            fma6(wr.z, wz.z, wn.z, h1p[(kc * 4 + 2) * 8 + bp], ar, az, ahn, cr, cz, chn);
            fma6(wr.w, wz.w, wn.w, h1p[(kc * 4 + 3) * 8 + bp], ar, az, ahn, cr, cz, chn);
        }
#pragma unroll 2
        for (int kc = 0; kc < ND / 4; kc++) {
            float4 wr = __ldg(w1r_x + kc), wz = __ldg(w1z_x + kc), wn = __ldg(w1n_x + kc);
            fma6(wr.x, wz.x, wn.x, xp[(kc * 4 + 0) * 8 + bp], ar, az, ain, cr, cz, cin);
            fma6(wr.y, wz.y, wn.y, xp[(kc * 4 + 1) * 8 + bp], ar, az, ain, cr, cz, cin);
            fma6(wr.z, wz.z, wn.z, xp[(kc * 4 + 2) * 8 + bp], ar, az, ain, cr, cz, cin);
            fma6(wr.w, wz.w, wn.w, xp[(kc * 4 + 3) * 8 + bp], ar, az, ain, cr, cz, cin);
        }
        {
            float h0 = sh_h1[j1 * BPG + 2 * bp];
            float h1o = sh_h1[j1 * BPG + 2 * bp + 1];
            float r0 = sigf(ar), z0 = sigf(az);
            float n0 = tanhf(ain + r0 * ahn);
            float r1 = sigf(cr), z1 = sigf(cz);
            float n1 = tanhf(cin + r1 * chn);
            float2 st = make_float2((1.f - z0) * n0 + z0 * h0,
                                    (1.f - z1) * n1 + z1 * h1o);
            *(float2*)(g_h1x + ((size_t)(par * NG + g) * NH + j1) * BPG + 2 * bp) = st;
        }
        cluster_sync_all();
        {
            const float4* src = (const float4*)(g_h1x + (size_t)(par * NG + g) * NH * BPG);
            float4* dst = (float4*)sh_h1;
            for (int p = 0; p < 4; p++) dst[tid + p * 256] = __ldcg(src + tid + p * 256);
        }
        __syncthreads();

        // enc2: x = new h1 (smem), h = sh_h2
        if (tid < 128) {
            float dr = b2r, dz = b2z, din = b2in, dhn = b2hn;
            float er = b2r, ez = b2z, ein = b2in, ehn = b2hn;
#pragma unroll 2
            for (int kc = 0; kc < NHH / 4; kc++) {
                float4 wr = __ldg(w2r_h + kc), wz = __ldg(w2z_h + kc), wn = __ldg(w2n_h + kc);
                fma6(wr.x, wz.x, wn.x, h2p[(kc * 4 + 0) * 8 + bp], dr, dz, dhn, er, ez, ehn);
                fma6(wr.y, wz.y, wn.y, h2p[(kc * 4 + 1) * 8 + bp], dr, dz, dhn, er, ez, ehn);
                fma6(wr.z, wz.z, wn.z, h2p[(kc * 4 + 2) * 8 + bp], dr, dz, dhn, er, ez, ehn);
                fma6(wr.w, wz.w, wn.w, h2p[(kc * 4 + 3) * 8 + bp], dr, dz, dhn, er, ez, ehn);
            }
#pragma unroll 2
            for (int kc = 0; kc < NH / 4; kc++) {
                float4 wr = __ldg(w2r_x + kc), wz = __ldg(w2z_x + kc), wn = __ldg(w2n_x + kc);
                fma6(wr.x, wz.x, wn.x, h1p[(kc * 4 + 0) * 8 + bp], dr, dz, din, er, ez, ein);
                fma6(wr.y, wz.y, wn.y, h1p[(kc * 4 + 1) * 8 + bp], dr, dz, din, er, ez, ein);
                fma6(wr.z, wz.z, wn.z, h1p[(kc * 4 + 2) * 8 + bp], dr, dz, din, er, ez, ein);
                fma6(wr.w, wz.w, wn.w, h1p[(kc * 4 + 3) * 8 + bp], dr, dz, din, er, ez, ein);
            }
            float h0 = sh_h2[j2 * BPG + 2 * bp];
            float h1o = sh_h2[j2 * BPG + 2 * bp + 1];
            float r0 = sigf(dr), z0 = sigf(dz);
            float n0 = tanhf(din + r0 * dhn);
            float r1 = sigf(er), z1 = sigf(ez);
            float n1 = tanhf(ein + r1 * ehn);
            float2 st = make_float2((1.f - z0) * n0 + z0 * h0,
                                    (1.f - z1) * n1 + z1 * h1o);
            *(float2*)(g_h2x + ((size_t)(par * NG + g) * NHH + j2) * BPG + 2 * bp) = st;
        }
        cluster_sync_all();
        {
            const float4* src = (const float4*)(g_h2x + (size_t)(par * NG + g) * NHH * BPG);
            float4* dst = (float4*)sh_h2;
            for (int p = 0; p < 2; p++) dst[tid + p * 256] = __ldcg(src + tid + p * 256);
        }
        __syncthreads();
    }
}

// ---------------- latent = h2_final @ l1_W^T + l1_b (h2_final in g_h2x par=1) ----------------
__global__ __launch_bounds__(256) void latent_kernel(const float* __restrict__ W,
                                                     const float* __restrict__ bias,
                                                     float* __restrict__ dout) {
    int id = blockIdx.x * 256 + threadIdx.x;   // 16384
    int l = id >> 8;
    int b = id & 255;
    int g = b >> 4, bb = b & 15;
    const float* h = g_h2x + (size_t)(NG + g) * NHH * BPG;   // par = 1 (t = 511)
    float acc = bias[l];
    const float* w = W + (size_t)l * NHH;
#pragma unroll 4
    for (int k = 0; k < NHH; k++) acc += w[k] * h[k * BPG + bb];
    g_lat[b * NL + l] = acc;
    dout[b * NL + l] = acc;
}

// ---------------- decoder constant gi1 = latent @ d1_Wih^T + d1_bih ----------------
__global__ __launch_bounds__(256) void gi1_kernel(const float* __restrict__ Wih,
                                                  const float* __restrict__ bih) {
    int id = blockIdx.x * 256 + threadIdx.x;   // 98304
    int b = id / (3 * NHH);
    int r = id % (3 * NHH);
    const float* w = Wih + (size_t)r * NL;
    const float* v = g_lat + (size_t)b * NL;
    float acc = bih[r];
#pragma unroll
    for (int k = 0; k < NL; k++) acc += w[k] * v[k];
    g_gi1[id] = acc;
}

// ======================= DECODER: persistent over all 512 steps =======================
__global__ __launch_bounds__(256, 1) __cluster_dims__(CLU, 1, 1)
void dec_kernel(const float* __restrict__ d1_Whh, const float* __restrict__ d1_bhh,
                const float* __restrict__ d2_Wih, const float* __restrict__ d2_Whh,
                const float* __restrict__ d2_bih, const float* __restrict__ d2_bhh) {
    __shared__ float sh_hd1[NHH * BPG];   // 8 KB
    __shared__ float sh_hd2[NH * BPG];    // 16 KB

    const int tid = threadIdx.x;
    const int rank = blockIdx.x & (CLU - 1);
    const int g = blockIdx.x >> 3;
    const int bp = tid & 7;

    {
        float4 z = make_float4(0.f, 0.f, 0.f, 0.f);
        float4* h1 = (float4*)sh_hd1;
        float4* h2 = (float4*)sh_hd2;
        for (int p = 0; p < 2; p++) h1[tid + p * 256] = z;
        for (int p = 0; p < 4; p++) h2[tid + p * 256] = z;
    }

    const int jA = rank * 16 + (tid >> 3);        // dec1 j (tid<128)
    float gir0 = 0, giz0 = 0, gin0 = 0, gir1 = 0, giz1 = 0, gin1 = 0;
    float bd1r = 0, bd1z = 0, bd1hn = 0;
    const float4 *wAr = 0, *wAz = 0, *wAn = 0;
    if (tid < 128) {
        int b0 = g * BPG + 2 * bp, b1 = b0 + 1;
        gir0 = g_gi1[(size_t)b0 * 3 * NHH + jA];
        giz0 = g_gi1[(size_t)b0 * 3 * NHH + NHH + jA];
        gin0 = g_gi1[(size_t)b0 * 3 * NHH + 2 * NHH + jA];
        gir1 = g_gi1[(size_t)b1 * 3 * NHH + jA];
        giz1 = g_gi1[(size_t)b1 * 3 * NHH + NHH + jA];
        gin1 = g_gi1[(size_t)b1 * 3 * NHH + 2 * NHH + jA];
        bd1r = d1_bhh[jA];
        bd1z = d1_bhh[NHH + jA];
        bd1hn = d1_bhh[2 * NHH + jA];
        wAr = (const float4*)(d1_Whh + (size_t)jA * NHH);
        wAz = (const float4*)(d1_Whh + (size_t)(NHH + jA) * NHH);
        wAn = (const float4*)(d1_Whh + (size_t)(2 * NHH + jA) * NHH);
    }

    const int jB = rank * 32 + (tid >> 3);        // dec2 j
    const float b2r  = d2_bih[jB] + d2_bhh[jB];
    const float b2z  = d2_bih[NH + jB] + d2_bhh[NH + jB];
    const float b2in = d2_bih[2 * NH + jB];
    const float b2hn = d2_bhh[2 * NH + jB];
    const float4* wBr_h = (const float4*)(d2_Whh + (size_t)jB * NH);
    const float4* wBz_h = (const float4*)(d2_Whh + (size_t)(NH + jB) * NH);
    const float4* wBn_h = (const float4*)(d2_Whh + (size_t)(2 * NH + jB) * NH);
    const float4* wBr_x = (const float4*)(d2_Wih + (size_t)jB * NHH);
    const float4* wBz_x = (const float4*)(d2_Wih + (size_t)(NH + jB) * NHH);
    const float4* wBn_x = (const float4*)(d2_Wih + (size_t)(2 * NH + jB) * NHH);
    __syncthreads();

    const float2* hd1p = (const float2*)sh_hd1;
    const float2* hd2p = (const float2*)sh_hd2;

    for (int t = 0; t < NS; t++) {
        const int par = t & 1;

        // dec1
        if (tid < 128) {
            float ar0 = gir0 + bd1r, az0 = giz0 + bd1z, ahn0 = bd1hn;
            float ar1 = gir1 + bd1r, az1 = giz1 + bd1z, ahn1 = bd1hn;
#pragma unroll 2
            for (int kc = 0; kc < NHH / 4; kc++) {
                float4 wr = __ldg(wAr + kc), wz = __ldg(wAz + kc), wn = __ldg(wAn + kc);
                fma6(wr.x, wz.x, wn.x, hd1p[(kc * 4 + 0) * 8 + bp], ar0, az0, ahn0, ar1, az1, ahn1);
                fma6(wr.y, wz.y, wn.y, hd1p[(kc * 4 + 1) * 8 + bp], ar0, az0, ahn0, ar1, az1, ahn1);
                fma6(wr.z, wz.z, wn.z, hd1p[(kc * 4 + 2) * 8 + bp], ar0, az0, ahn0, ar1, az1, ahn1);
                fma6(wr.w, wz.w, wn.w, hd1p[(kc * 4 + 3) * 8 + bp], ar0, az0, ahn0, ar1, az1, ahn1);
            }
            float h0 = sh_hd1[jA * BPG + 2 * bp];
            float h1o = sh_hd1[jA * BPG + 2 * bp + 1];
            float r0 = sigf(ar0), z0 = sigf(az0);
            float n0 = tanhf(gin0 + r0 * ahn0);
            float r1 = sigf(ar1), z1 = sigf(az1);
            float n1 = tanhf(gin1 + r1 * ahn1);
            float2 st = make_float2((1.f - z0) * n0 + z0 * h0,
                                    (1.f - z1) * n1 + z1 * h1o);
            *(float2*)(g_hd1x + ((size_t)(par * NG + g) * NHH + jA) * BPG + 2 * bp) = st;
        }
        cluster_sync_all();
        {
            const float4* src = (const float4*)(g_hd1x + (size_t)(par * NG + g) * NHH * BPG);
            float4* dst = (float4*)sh_hd1;
            for (int p = 0; p < 2; p++) dst[tid + p * 256] = __ldcg(src + tid + p * 256);
        }
        __syncthreads();

        // dec2: x = new hd1, h = sh_hd2
        {
            float ar = b2r, az = b2z, ain = b2in, ahn = b2hn;
            float cr = b2r, cz = b2z, cin = b2in, chn = b2hn;
#pragma unroll 2
            for (int kc = 0; kc < NH / 4; kc++) {
                float4 wr = __ldg(wBr_h + kc), wz = __ldg(wBz_h + kc), wn = __ldg(wBn_h + kc);
                fma6(wr.x, wz.x, wn.x, hd2p[(kc * 4 + 0) * 8 + bp], ar, az, ahn, cr, cz, chn);
                fma6(wr.y, wz.y, wn.y, hd2p[(kc * 4 + 1) * 8 + bp], ar, az, ahn, cr, cz, chn);
                fma6(wr.z, wz.z, wn.z, hd2p[(kc * 4 + 2) * 8 + bp], ar, az, ahn, cr, cz, chn);
                fma6(wr.w, wz.w, wn.w, hd2p[(kc * 4 + 3) * 8 + bp], ar, az, ahn, cr, cz, chn);
            }
#pragma unroll 2
            for (int kc = 0; kc < NHH / 4; kc++) {
                float4 wr = __ldg(wBr_x + kc), wz = __ldg(wBz_x + kc), wn = __ldg(wBn_x + kc);
                fma6(wr.x, wz.x, wn.x, hd1p[(kc * 4 + 0) * 8 + bp], ar, az, ain, cr, cz, cin);
                fma6(wr.y, wz.y, wn.y, hd1p[(kc * 4 + 1) * 8 + bp], ar, az, ain, cr, cz, cin);
                fma6(wr.z, wz.z, wn.z, hd1p[(kc * 4 + 2) * 8 + bp], ar, az, ain, cr, cz, cin);
                fma6(wr.w, wz.w, wn.w, hd1p[(kc * 4 + 3) * 8 + bp], ar, az, ain, cr, cz, cin);
            }
            float h0 = sh_hd2[jB * BPG + 2 * bp];
            float h1o = sh_hd2[jB * BPG + 2 * bp + 1];
            float r0 = sigf(ar), z0 = sigf(az);
            float n0 = tanhf(ain + r0 * ahn);
            float r1 = sigf(cr), z1 = sigf(cz);
            float n1 = tanhf(cin + r1 * chn);
            float2 st = make_float2((1.f - z0) * n0 + z0 * h0,
                                    (1.f - z1) * n1 + z1 * h1o);
            *(float2*)(g_hd2x + ((size_t)(par * NG + g) * NH + jB) * BPG + 2 * bp) = st;
            *(float2*)(g_h2seq + ((size_t)(t * NG + g) * NH + jB) * BPG + 2 * bp) = st;
        }
        cluster_sync_all();
        {
            const float4* src = (const float4*)(g_hd2x + (size_t)(par * NG + g) * NH * BPG);
            float4* dst = (float4*)sh_hd2;
            for (int p = 0; p < 4; p++) dst[tid + p * 256] = __ldcg(src + tid + p * 256);
        }
        __syncthreads();
    }
}

// ---------------- l2 projection + MSE loss: CTA = (t, g) ----------------
__global__ __launch_bounds__(256) void l2loss_kernel(const float* __restrict__ W,
                                                     const float* __restrict__ bias) {
    __shared__ float shW[64 * 128];   // [k][d] 32 KB
    __shared__ float shH[64 * BPG];   // [k][b] 4 KB
    __shared__ double sred[8];
    const int t = blockIdx.x >> 4;
    const int g = blockIdx.x & 15;
    const int tid = threadIdx.x;
    const int d = tid & 127;
    const int half = tid >> 7;

    float acc[8];
#pragma unroll
    for (int i = 0; i < 8; i++) acc[i] = bias[d];

    const float4* W4 = (const float4*)W;          // W rows: 64 float4 (NH=256)
    const float4* H4 = (const float4*)g_h2seq;

    for (int kt = 0; kt < 4; kt++) {
        for (int p = 0; p < 8; p++) {             // stage W[k][d] transposed
            int idx = tid + p * 256;
            int dd = idx >> 4, kc = idx & 15;
            float4 v = __ldg(W4 + (size_t)dd * 64 + kt * 16 + kc);
            shW[(kc * 4 + 0) * 128 + dd] = v.x;
            shW[(kc * 4 + 1) * 128 + dd] = v.y;
            shW[(kc * 4 + 2) * 128 + dd] = v.z;
            shW[(kc * 4 + 3) * 128 + dd] = v.w;
        }
        ((float4*)shH)[tid] = __ldg(H4 + ((size_t)(t * NG + g) * NH + kt * 64) * 4 + tid);
        __syncthreads();
#pragma unroll 4
        for (int k = 0; k < 64; k++) {
            float w = shW[k * 128 + d];
            float4 hA = *(const float4*)&shH[k * BPG + half * 8];
            float4 hB = *(const float4*)&shH[k * BPG + half * 8 + 4];
            acc[0] += w * hA.x; acc[1] += w * hA.y; acc[2] += w * hA.z; acc[3] += w * hA.w;
            acc[4] += w * hB.x; acc[5] += w * hB.y; acc[6] += w * hB.z; acc[7] += w * hB.w;
        }
        __syncthreads();
    }

    float se = 0.f;
#pragma unroll
    for (int i = 0; i < 8; i++) {
        int b = g * BPG + half * 8 + i;
        float e = g_emb[((size_t)b * NS + t) * ND + d];
        float diff = acc[i] - e;
        se += diff * diff;
    }
    for (int o = 16; o > 0; o >>= 1) se += __shfl_down_sync(0xffffffffu, se, o);
    if ((tid & 31) == 0) sred[tid >> 5] = (double)se;
    __syncthreads();
    if (tid == 0) {
        double s = 0;
        for (int i = 0; i < 8; i++) s += sred[i];
        atomicAdd(&g_losspart[blockIdx.x & 1023], s);
    }
}

// ---------------- finalize ----------------
__global__ void final_kernel(float* __restrict__ dout) {
    __shared__ double s[256];
    int tid = threadIdx.x;
    double v = g_losspart[tid] + g_losspart[tid + 256] + g_losspart[tid + 512] + g_losspart[tid + 768];
    s[tid] = v;
    __syncthreads();
    for (int o = 128; o > 0; o >>= 1) {
        if (tid < o) s[tid] += s[tid + o];
        __syncthreads();
    }
    if (tid == 0) dout[NB * NL] = (float)(s[0] / (double)((size_t)NB * NS * ND));
}

// ---------------- launch ----------------
extern "C" void kernel_launch(void* const* d_in, const int* in_sizes, int n_in,
                              void* d_out, int out_size) {
    const int*   tok     = (const int*)d_in[0];
    const float* path_w  = (const float*)d_in[1];
    const float* sys_w   = (const float*)d_in[2];
    const float* e1_Wih  = (const float*)d_in[3];
    const float* e1_Whh  = (const float*)d_in[4];
    const float* e1_bih  = (const float*)d_in[5];
    const float* e1_bhh  = (const float*)d_in[6];
    const float* e2_Wih  = (const float*)d_in[7];
    const float* e2_Whh  = (const float*)d_in[8];
    const float* e2_bih  = (const float*)d_in[9];
    const float* e2_bhh  = (const float*)d_in[10];
    const float* l1_W    = (const float*)d_in[11];
    const float* l1_b    = (const float*)d_in[12];
    const float* d1_Wih  = (const float*)d_in[13];
    const float* d1_Whh  = (const float*)d_in[14];
    const float* d1_bih  = (const float*)d_in[15];
    const float* d1_bhh  = (const float*)d_in[16];
    const float* d2_Wih  = (const float*)d_in[17];
    const float* d2_Whh  = (const float*)d_in[18];
    const float* d2_bih  = (const float*)d_in[19];
    const float* d2_bhh  = (const float*)d_in[20];
    const float* l2_W    = (const float*)d_in[21];
    const float* l2_b    = (const float*)d_in[22];
    float* dout = (float*)d_out;

    init_kernel<<<4, 256>>>();
    emb_kernel<<<4096, 256>>>(tok, path_w, sys_w);
    enc_kernel<<<NG * CLU, 256>>>(e1_Wih, e1_Whh, e1_bih, e1_bhh,
                                  e2_Wih, e2_Whh, e2_bih, e2_bhh);
    latent_kernel<<<64, 256>>>(l1_W, l1_b, dout);
    gi1_kernel<<<384, 256>>>(d1_Wih, d1_bih);
    dec_kernel<<<NG * CLU, 256>>>(d1_Whh, d1_bhh, d2_Wih, d2_Whh, d2_bih, d2_bhh);
    l2loss_kernel<<<NS * NG, 256>>>(l2_W, l2_b);
    final_kernel<<<1, 256>>>(dout);
}